// round 16
// baseline (speedup 1.0000x reference)
#include <cuda_runtime.h>
#include <cuda_fp16.h>
#include <cstdint>

// TEPRNN2 via warp MMA (HMMA): gates = W_hh x h (K=64, fp16 hi/lo 3-MMA) + gx,
// gx = W_ih*fc1 + bias in exact fp32 as accumulator init; tanh.approx epilogue.
// R15: 8-batch CTAs, 4 independent CTAs/SM (regs<=128 via Al/W_ih/bias in SMEM
// reloaded with per-thread conflict-free LDS.128); ONE sync per step.

#define S_LEN   256
#define THREADS 128
#define BPB     8
#define HST     72          // halfs per batch column (64 + 8 pad)

__device__ __forceinline__ uint32_t pk(float a, float b){
    __half2 t = __halves2half2(__float2half_rn(a), __float2half_rn(b));
    return *reinterpret_cast<uint32_t*>(&t);
}
__device__ __forceinline__ void mma16816(float* d, const uint32_t* a,
                                         uint32_t b0, uint32_t b1){
    asm volatile(
        "mma.sync.aligned.m16n8k16.row.col.f32.f16.f16.f32 "
        "{%0,%1,%2,%3}, {%4,%5,%6,%7}, {%8,%9}, {%0,%1,%2,%3};"
        : "+f"(d[0]), "+f"(d[1]), "+f"(d[2]), "+f"(d[3])
        : "r"(a[0]), "r"(a[1]), "r"(a[2]), "r"(a[3]), "r"(b0), "r"(b1));
}
__device__ __forceinline__ void mma16816v(float* d, uint4 a,
                                          uint32_t b0, uint32_t b1){
    asm volatile(
        "mma.sync.aligned.m16n8k16.row.col.f32.f16.f16.f32 "
        "{%0,%1,%2,%3}, {%4,%5,%6,%7}, {%8,%9}, {%0,%1,%2,%3};"
        : "+f"(d[0]), "+f"(d[1]), "+f"(d[2]), "+f"(d[3])
        : "r"(a.x), "r"(a.y), "r"(a.z), "r"(a.w), "r"(b0), "r"(b1));
}
__device__ __forceinline__ float htanh(float x){
    float r;
    asm("tanh.approx.f32 %0, %1;" : "=f"(r) : "f"(x));
    return r;
}
__device__ __forceinline__ float hsigm(float x){   // sigma(x) = 0.5 + 0.5*tanh(x/2)
    return fmaf(0.5f, htanh(0.5f * x), 0.5f);
}

__global__ __launch_bounds__(THREADS, 4)
void teprnn2_mma(const float* __restrict__ x,
                 const float* __restrict__ W1,
                 const float* __restrict__ b1,
                 const float* __restrict__ W_ih,
                 const float* __restrict__ W_hh,
                 const float* __restrict__ b_ih,
                 const float* __restrict__ b_hh,
                 const float* __restrict__ W2,
                 const float* __restrict__ b2,
                 float* __restrict__ out)
{
    __shared__ __half  hHI[2][8][HST];       // [buf][batch-col][k]
    __shared__ __half  hLO[2][8][HST];
    __shared__ float   fc1f[2][8][4];        // [buf][batch-col][feat]
    __shared__ uint4   AlS[4 * 4 * 4 * 32];  // [ub][kt][g][lane] 16B slots
    __shared__ float4  wihS[4][8][4][2];     // [ub][r0][g][rr]
    __shared__ float2  bseS[4][8][4];        // [ub][r0][g] = (rr0, rr1)

    const int tid  = threadIdx.x;
    const int ub   = tid >> 5;     // warp = unit block (16 units)
    const int lane = tid & 31;
    const int r0   = lane >> 2;
    const int k0   = (lane & 3) * 2;
    const int bbase = blockIdx.x * BPB;

    // ---- A fragments: Ah (W_hh hi) in regs; Al (W_hh lo) into SMEM ----
    uint32_t Ah[4][4][4];
    #pragma unroll
    for (int g = 0; g < 4; ++g) {
        const int gr0 = g * 64 + ub * 16 + r0;
        #pragma unroll
        for (int kt = 0; kt < 4; ++kt) {
            const int kb = kt * 16 + k0;
            float v[8];
            v[0] = W_hh[gr0 * 64 + kb];        v[1] = W_hh[gr0 * 64 + kb + 1];
            v[2] = W_hh[(gr0+8) * 64 + kb];    v[3] = W_hh[(gr0+8) * 64 + kb + 1];
            v[4] = W_hh[gr0 * 64 + kb + 8];    v[5] = W_hh[gr0 * 64 + kb + 9];
            v[6] = W_hh[(gr0+8) * 64 + kb + 8];v[7] = W_hh[(gr0+8) * 64 + kb + 9];
            float hi[8], lo[8];
            #pragma unroll
            for (int e = 0; e < 8; ++e) {
                hi[e] = __half2float(__float2half_rn(v[e]));
                lo[e] = v[e] - hi[e];
            }
            Ah[g][kt][0] = pk(hi[0], hi[1]);
            Ah[g][kt][1] = pk(hi[2], hi[3]);
            Ah[g][kt][2] = pk(hi[4], hi[5]);
            Ah[g][kt][3] = pk(hi[6], hi[7]);
            uint4 alv;
            alv.x = pk(lo[0], lo[1]);
            alv.y = pk(lo[2], lo[3]);
            alv.z = pk(lo[4], lo[5]);
            alv.w = pk(lo[6], lo[7]);
            AlS[((ub * 16 + kt * 4 + g) << 5) + lane] = alv;
        }
    }

    // ---- W_ih + combined bias into SMEM (one lane per (ub, r0)) ----
    if ((lane & 3) == 0) {
        #pragma unroll
        for (int g = 0; g < 4; ++g) {
            float2 bs;
            #pragma unroll
            for (int rr = 0; rr < 2; ++rr) {
                const int row = g * 64 + ub * 16 + r0 + rr * 8;
                float4 w4;
                w4.x = W_ih[row * 4 + 0]; w4.y = W_ih[row * 4 + 1];
                w4.z = W_ih[row * 4 + 2]; w4.w = W_ih[row * 4 + 3];
                wihS[ub][r0][g][rr] = w4;
                ((float*)&bs)[rr] = b_ih[row] + b_hh[row];
            }
            bseS[ub][r0][g] = bs;
        }
    }

    // ---- fc1 duty: threads 0..31 (8 batches x 4 features) ----
    const int lb = tid >> 2;         // batch col (tid < 32)
    const int fi = tid & 3;
    const float w1r = __ldg(W1 + (tid < 32 ? fi : 0));
    const float b1r = __ldg(b1 + (tid < 32 ? fi : 0));
    const float* xrow = x + (size_t)(bbase + (tid < 32 ? lb : 0)) * S_LEN;

    {   // zero h arrays
        __half* p0 = &hHI[0][0][0];
        __half* p1 = &hLO[0][0][0];
        for (int i = tid; i < 2 * 8 * HST; i += THREADS) {
            p0[i] = __ushort_as_half(0); p1[i] = __ushort_as_half(0);
        }
    }
    if (tid < 32) {
        fc1f[0][lb][fi] = htanh(fmaf(__ldg(xrow + 0), w1r, b1r));
    }
    __syncthreads();

    // ---- stagger co-resident CTAs (one-time seed) ----
    {
        const int iters = (blockIdx.x & 3) * 80;
        float dmy = __ldg(b2);
        #pragma unroll 1
        for (int i = 0; i < iters; ++i) dmy = fmaf(dmy, 0.999f, 1.0f);
        if (tid == 0 && iters)
            hLO[0][0][64] = __float2half_rn(dmy * 0.0f);   // pad slot, value 0
    }

    float cst[4];
    #pragma unroll
    for (int e = 0; e < 4; ++e) cst[e] = 0.f;

    for (int s = 0; s < S_LEN; ++s) {
        const int buf  = s & 1;
        const int nbuf = buf ^ 1;

        float xv = (s + 1 < S_LEN && tid < 32) ? __ldg(xrow + s + 1) : 0.f;

        // ---- gx = W_ih*fc1 + bias as accumulator init (exact fp32) ----
        float d[4][4];
        {
            const float4 f40 = *(const float4*)&fc1f[buf][k0][0];
            const float4 f41 = *(const float4*)&fc1f[buf][k0 + 1][0];
            #pragma unroll
            for (int g = 0; g < 4; ++g) {
                const float2 bs = bseS[ub][r0][g];
                const float4 w0 = wihS[ub][r0][g][0];
                const float4 w1 = wihS[ub][r0][g][1];
                d[g][0] = fmaf(w0.x, f40.x, fmaf(w0.y, f40.y,
                          fmaf(w0.z, f40.z, fmaf(w0.w, f40.w, bs.x))));
                d[g][1] = fmaf(w0.x, f41.x, fmaf(w0.y, f41.y,
                          fmaf(w0.z, f41.z, fmaf(w0.w, f41.w, bs.x))));
                d[g][2] = fmaf(w1.x, f40.x, fmaf(w1.y, f40.y,
                          fmaf(w1.z, f40.z, fmaf(w1.w, f40.w, bs.y))));
                d[g][3] = fmaf(w1.x, f41.x, fmaf(w1.y, f41.y,
                          fmaf(w1.z, f41.z, fmaf(w1.w, f41.w, bs.y))));
            }
        }

        // ---- MMA phase: 48 HMMAs (Ah.Bh + Al.Bh + Ah.Bl per tile) ----
        {
            const __half* bhp = &hHI[buf][0][0];
            const __half* blp = &hLO[buf][0][0];
            #pragma unroll
            for (int kt = 0; kt < 4; ++kt) {
                const int idx = r0 * HST + kt * 16 + k0;
                uint32_t bh0 = *(const uint32_t*)(bhp + idx);
                uint32_t bh1 = *(const uint32_t*)(bhp + idx + 8);
                uint32_t bl0 = *(const uint32_t*)(blp + idx);
                uint32_t bl1 = *(const uint32_t*)(blp + idx + 8);
                #pragma unroll
                for (int g = 0; g < 4; ++g) {
                    mma16816(d[g], Ah[g][kt], bh0, bh1);
                    mma16816v(d[g], AlS[((ub * 16 + kt * 4 + g) << 5) + lane],
                              bh0, bh1);
                    mma16816(d[g], Ah[g][kt], bl0, bl1);
                }
            }
        }

        // ---- LSTM epilogue (tanh.approx) ----
        #pragma unroll
        for (int e = 0; e < 4; ++e) {
            float si = hsigm(d[0][e]);
            float ff = hsigm(d[1][e]);
            float tg = htanh(d[2][e]);
            float oo = hsigm(d[3][e]);
            float cc = fmaf(ff, cst[e], si * tg);
            cst[e] = cc;
            float hh = oo * htanh(cc);
            const int u  = ub * 16 + r0 + ((e >= 2) ? 8 : 0);
            const int cl = k0 + (e & 1);
            float hhi = __half2float(__float2half_rn(hh));
            hHI[nbuf][cl][u] = __float2half_rn(hh);
            hLO[nbuf][cl][u] = __float2half_rn(hh - hhi);
        }

        // fc1 for step s+1 -> nbuf
        if (s + 1 < S_LEN && tid < 32)
            fc1f[nbuf][lb][fi] = htanh(fmaf(xv, w1r, b1r));

        __syncthreads();   // single barrier per step
    }

    // ---- fc2: h reconstructed from hi+lo (final h in buffer 0) ----
    if (tid < 8) {
        const __half* hi = &hHI[0][tid][0];
        const __half* lo = &hLO[0][tid][0];
        float acc = __ldg(b2);
        #pragma unroll
        for (int u = 0; u < 64; ++u)
            acc = fmaf(__ldg(W2 + u),
                       __half2float(hi[u]) + __half2float(lo[u]), acc);
        out[bbase + tid] = acc;
    }
}

extern "C" void kernel_launch(void* const* d_in, const int* in_sizes, int n_in,
                              void* d_out, int out_size)
{
    const float* x    = (const float*)d_in[0];
    const float* W1   = (const float*)d_in[1];
    const float* b1   = (const float*)d_in[2];
    const float* W_ih = (const float*)d_in[3];
    const float* W_hh = (const float*)d_in[4];
    const float* b_ih = (const float*)d_in[5];
    const float* b_hh = (const float*)d_in[6];
    const float* W2   = (const float*)d_in[7];
    const float* b2   = (const float*)d_in[8];
    float* out = (float*)d_out;

    teprnn2_mma<<<4096 / BPB, THREADS>>>(
        x, W1, b1, W_ih, W_hh, b_ih, b_hh, W2, b2, out);
}

// round 17
// speedup vs baseline: 1.4117x; 1.4117x over previous
#include <cuda_runtime.h>
#include <cuda_fp16.h>
#include <cstdint>

// TEPRNN2 via warp MMA (HMMA): gates = W_hh x h (K=64, fp16 hi/lo 3-MMA) + gx,
// gx = W_ih*fc1 + bias in exact fp32 as accumulator init; tanh.approx epilogue.
// R17: R14 base + MMA/EPI fine interleave with DEFERRED stores — EPI MUFU
// chains issue between MMA chunks and complete under later MMA issue; the
// dependent STS block runs only after all chunks (no tensor-idling stalls).

#define S_LEN   256
#define THREADS 128
#define BPB     16
#define HST     72          // halfs per batch column (64 + 8 pad; conflict-free)

__device__ __forceinline__ uint32_t pk(float a, float b){
    __half2 t = __halves2half2(__float2half_rn(a), __float2half_rn(b));
    return *reinterpret_cast<uint32_t*>(&t);
}
__device__ __forceinline__ void mma16816(float* d, const uint32_t* a,
                                         uint32_t b0, uint32_t b1){
    asm volatile(
        "mma.sync.aligned.m16n8k16.row.col.f32.f16.f16.f32 "
        "{%0,%1,%2,%3}, {%4,%5,%6,%7}, {%8,%9}, {%0,%1,%2,%3};"
        : "+f"(d[0]), "+f"(d[1]), "+f"(d[2]), "+f"(d[3])
        : "r"(a[0]), "r"(a[1]), "r"(a[2]), "r"(a[3]), "r"(b0), "r"(b1));
}
__device__ __forceinline__ float htanh(float x){
    float r;
    asm("tanh.approx.f32 %0, %1;" : "=f"(r) : "f"(x));
    return r;
}
__device__ __forceinline__ float hsigm(float x){   // sigma(x) = 0.5 + 0.5*tanh(x/2)
    return fmaf(0.5f, htanh(0.5f * x), 0.5f);
}

__global__ __launch_bounds__(THREADS, 2)
void teprnn2_mma(const float* __restrict__ x,
                 const float* __restrict__ W1,
                 const float* __restrict__ b1,
                 const float* __restrict__ W_ih,
                 const float* __restrict__ W_hh,
                 const float* __restrict__ b_ih,
                 const float* __restrict__ b_hh,
                 const float* __restrict__ W2,
                 const float* __restrict__ b2,
                 float* __restrict__ out)
{
    __shared__ __half hHI[2][16][HST];   // [buf][batch-col][k]
    __shared__ __half hLO[2][16][HST];
    __shared__ float  fc1f[2][16][4];    // [buf][batch-col][feat] fp32

    const int tid  = threadIdx.x;
    const int ub   = tid >> 5;     // warp = unit block (16 units)
    const int lane = tid & 31;
    const int r0   = lane >> 2;
    const int k0   = (lane & 3) * 2;
    const int bbase = blockIdx.x * BPB;

    // ---- A fragments (W_hh only): Ah/Al[gate][ktile(4)][4] ----
    uint32_t Ah[4][4][4], Al[4][4][4];
    #pragma unroll
    for (int g = 0; g < 4; ++g) {
        const int gr0 = g * 64 + ub * 16 + r0;
        #pragma unroll
        for (int kt = 0; kt < 4; ++kt) {
            const int kb = kt * 16 + k0;
            float v[8];
            v[0] = W_hh[gr0 * 64 + kb];        v[1] = W_hh[gr0 * 64 + kb + 1];
            v[2] = W_hh[(gr0+8) * 64 + kb];    v[3] = W_hh[(gr0+8) * 64 + kb + 1];
            v[4] = W_hh[gr0 * 64 + kb + 8];    v[5] = W_hh[gr0 * 64 + kb + 9];
            v[6] = W_hh[(gr0+8) * 64 + kb + 8];v[7] = W_hh[(gr0+8) * 64 + kb + 9];
            float hi[8], lo[8];
            #pragma unroll
            for (int e = 0; e < 8; ++e) {
                hi[e] = __half2float(__float2half_rn(v[e]));
                lo[e] = v[e] - hi[e];
            }
            Ah[g][kt][0] = pk(hi[0], hi[1]);  Al[g][kt][0] = pk(lo[0], lo[1]);
            Ah[g][kt][1] = pk(hi[2], hi[3]);  Al[g][kt][1] = pk(lo[2], lo[3]);
            Ah[g][kt][2] = pk(hi[4], hi[5]);  Al[g][kt][2] = pk(lo[4], lo[5]);
            Ah[g][kt][3] = pk(hi[6], hi[7]);  Al[g][kt][3] = pk(lo[6], lo[7]);
        }
    }

    // ---- W_ih + combined bias for this thread's 2 unit rows (exact fp32) ----
    float wih[2][4][4], bse[2][4];
    #pragma unroll
    for (int rr = 0; rr < 2; ++rr)
        #pragma unroll
        for (int g = 0; g < 4; ++g) {
            const int row = g * 64 + ub * 16 + r0 + rr * 8;
            #pragma unroll
            for (int i = 0; i < 4; ++i) wih[rr][g][i] = W_ih[row * 4 + i];
            bse[rr][g] = b_ih[row] + b_hh[row];
        }

    // ---- fc1 duty: threads 0..63 (16 batches x 4 features) ----
    const int lb = tid >> 2;
    const int fi = tid & 3;
    const float w1r = __ldg(W1 + (tid < 64 ? fi : 0));
    const float b1r = __ldg(b1 + (tid < 64 ? fi : 0));
    const float* xrow = x + (size_t)(bbase + (tid < 64 ? lb : 0)) * S_LEN;

    {   // zero h arrays (h0 = 0; pads too)
        __half* p0 = &hHI[0][0][0];
        __half* p1 = &hLO[0][0][0];
        for (int i = tid; i < 2 * 16 * HST; i += THREADS) {
            p0[i] = __ushort_as_half(0); p1[i] = __ushort_as_half(0);
        }
    }
    if (tid < 64) {
        fc1f[0][lb][fi] = htanh(fmaf(__ldg(xrow + 0), w1r, b1r));
    }
    __syncthreads();

    // ---- seed anti-phase between the 2 co-resident CTAs (odd CTAs delay) ----
    if (blockIdx.x & 1) {
        float dmy = __ldg(b2);
        #pragma unroll 1
        for (int i = 0; i < 125; ++i) dmy = fmaf(dmy, 0.999f, 1.0f);
        if (tid == 0)
            hLO[0][0][64] = __float2half_rn(dmy * 0.0f);   // pad slot, value 0
    }

    float cst0[4], cst1[4];
    #pragma unroll
    for (int e = 0; e < 4; ++e) { cst0[e] = 0.f; cst1[e] = 0.f; }

    // ===== macros over local state =====
    #define GX_INIT(dd, nt, bf)                                               \
        {                                                                     \
            float4 f40 = *(const float4*)&fc1f[bf][(nt) * 8 + k0][0];         \
            float4 f41 = *(const float4*)&fc1f[bf][(nt) * 8 + k0 + 1][0];     \
            _Pragma("unroll")                                                 \
            for (int g = 0; g < 4; ++g) {                                     \
                _Pragma("unroll")                                             \
                for (int e = 0; e < 4; ++e) {                                 \
                    const int rr = e >> 1;                                    \
                    const float4 f4 = (e & 1) ? f41 : f40;                    \
                    float acc = bse[rr][g];                                   \
                    acc = fmaf(wih[rr][g][0], f4.x, acc);                     \
                    acc = fmaf(wih[rr][g][1], f4.y, acc);                     \
                    acc = fmaf(wih[rr][g][2], f4.z, acc);                     \
                    acc = fmaf(wih[rr][g][3], f4.w, acc);                     \
                    dd[g][e] = acc;                                           \
                }                                                             \
            }                                                                 \
        }

    // one kt-chunk of the MMA phase: 12 HMMAs
    #define MMA_KT(dd, nt, bf, kt)                                            \
        {                                                                     \
            const __half* bhp = &hHI[bf][0][0];                               \
            const __half* blp = &hLO[bf][0][0];                               \
            const int idx = ((nt) * 8 + r0) * HST + (kt) * 16 + k0;           \
            uint32_t bh0 = *(const uint32_t*)(bhp + idx);                     \
            uint32_t bh1 = *(const uint32_t*)(bhp + idx + 8);                 \
            uint32_t bl0 = *(const uint32_t*)(blp + idx);                     \
            uint32_t bl1 = *(const uint32_t*)(blp + idx + 8);                 \
            _Pragma("unroll")                                                 \
            for (int g = 0; g < 4; ++g) {                                     \
                mma16816(dd[g], Ah[g][kt], bh0, bh1);                         \
                mma16816(dd[g], Al[g][kt], bh0, bh1);                         \
                mma16816(dd[g], Ah[g][kt], bl0, bl1);                         \
            }                                                                 \
        }

    // EPI compute only (no SMEM stores): results to hsv/lsv register arrays
    #define EPI_COMP(dd, cstv, e, hsv, lsv)                                   \
        {                                                                     \
            float si = hsigm(dd[0][e]);                                       \
            float ff = hsigm(dd[1][e]);                                       \
            float tg = htanh(dd[2][e]);                                       \
            float oo = hsigm(dd[3][e]);                                       \
            float cc = fmaf(ff, cstv[e], si * tg);                            \
            cstv[e] = cc;                                                     \
            float hh = oo * htanh(cc);                                        \
            __half hhf = __float2half_rn(hh);                                 \
            hsv[e] = hhf;                                                     \
            lsv[e] = __float2half_rn(hh - __half2float(hhf));                 \
        }

    // deferred stores for all 4 elements
    #define EPI_STORE(nt, nbf, hsv, lsv)                                      \
        {                                                                     \
            _Pragma("unroll")                                                 \
            for (int e = 0; e < 4; ++e) {                                     \
                const int u  = ub * 16 + r0 + ((e >= 2) ? 8 : 0);             \
                const int cl = (nt) * 8 + k0 + (e & 1);                       \
                hHI[nbf][cl][u] = hsv[e];                                     \
                hLO[nbf][cl][u] = lsv[e];                                     \
            }                                                                 \
        }

    // ---- prologue: nt0 pipeline for step 0 ----
    float d0[4][4], d1[4][4];
    GX_INIT(d0, 0, 0);
    MMA_KT(d0, 0, 0, 0); MMA_KT(d0, 0, 0, 1);
    MMA_KT(d0, 0, 0, 2); MMA_KT(d0, 0, 0, 3);

    for (int s = 0; s < S_LEN; ++s) {
        const int buf  = s & 1;
        const int nbuf = buf ^ 1;
        __half hs[4], ls[4];

        float xv = (s + 1 < S_LEN && tid < 64) ? __ldg(xrow + s + 1) : 0.f;

        // --- half A: MMA(d1, step s) interleaved with EPI-compute(d0) ---
        GX_INIT(d1, 1, buf);
        MMA_KT(d1, 1, buf, 0);  EPI_COMP(d0, cst0, 0, hs, ls);
        MMA_KT(d1, 1, buf, 1);  EPI_COMP(d0, cst0, 1, hs, ls);
        MMA_KT(d1, 1, buf, 2);  EPI_COMP(d0, cst0, 2, hs, ls);
        MMA_KT(d1, 1, buf, 3);  EPI_COMP(d0, cst0, 3, hs, ls);
        EPI_STORE(0, nbuf, hs, ls);
        if (s + 1 < S_LEN && tid < 64)
            fc1f[nbuf][lb][fi] = htanh(fmaf(xv, w1r, b1r));

        __syncthreads();

        // --- half B: MMA(d0, step s+1) interleaved with EPI-compute(d1) ---
        GX_INIT(d0, 0, nbuf);
        MMA_KT(d0, 0, nbuf, 0); EPI_COMP(d1, cst1, 0, hs, ls);
        MMA_KT(d0, 0, nbuf, 1); EPI_COMP(d1, cst1, 1, hs, ls);
        MMA_KT(d0, 0, nbuf, 2); EPI_COMP(d1, cst1, 2, hs, ls);
        MMA_KT(d0, 0, nbuf, 3); EPI_COMP(d1, cst1, 3, hs, ls);
        EPI_STORE(1, nbuf, hs, ls);

        __syncthreads();
    }

    #undef GX_INIT
    #undef MMA_KT
    #undef EPI_COMP
    #undef EPI_STORE

    // ---- fc2: h reconstructed from hi+lo (final h in buffer 0) ----
    if (tid < 16) {
        const __half* hi = &hHI[0][tid][0];
        const __half* lo = &hLO[0][tid][0];
        float acc = __ldg(b2);
        #pragma unroll
        for (int u = 0; u < 64; ++u)
            acc = fmaf(__ldg(W2 + u),
                       __half2float(hi[u]) + __half2float(lo[u]), acc);
        out[bbase + tid] = acc;
    }
}

extern "C" void kernel_launch(void* const* d_in, const int* in_sizes, int n_in,
                              void* d_out, int out_size)
{
    const float* x    = (const float*)d_in[0];
    const float* W1   = (const float*)d_in[1];
    const float* b1   = (const float*)d_in[2];
    const float* W_ih = (const float*)d_in[3];
    const float* W_hh = (const float*)d_in[4];
    const float* b_ih = (const float*)d_in[5];
    const float* b_hh = (const float*)d_in[6];
    const float* W2   = (const float*)d_in[7];
    const float* b2   = (const float*)d_in[8];
    float* out = (float*)d_out;

    teprnn2_mma<<<4096 / BPB, THREADS>>>(
        x, W1, b1, W_ih, W_hh, b_ih, b_hh, W2, b2, out);
}